// round 8
// baseline (speedup 1.0000x reference)
#include <cuda_runtime.h>

#define BB  8
#define NP  2048
#define CI  64
#define CO  128
#define KK  16
#define NPART 8
#define CHUNK (NP / NPART)     // 256

// output layout: [ y (B*CO*N) | knn_mlp_x (B*CO*N*K) | local_coords (B*3*N*K) ]
#define KNN_OFF (BB*CO*NP)                 // 2,097,152
#define LC_OFF  (KNN_OFF + BB*CO*NP*KK)    // 35,651,584

#define FINF 3.402823466e38f

// scratch (no allocations allowed -> device globals)
__device__ int   g_idx[BB*NP*KK];              // 1 MB
__device__ float g_F[BB*NP*CO];                // 8 MB
__device__ float g_pd[BB*NP*NPART*KK];         // 8 MB partial top-16 dists
__device__ int   g_pi[BB*NP*NPART*KK];         // 8 MB partial top-16 idx

// ---------------------------------------------------------------------------
// Kernel 1a: partial KNN. Each thread: one (query, chunk-of-256) pair,
// stable top-16 by (d2, idx) — idx ascending within chunk so strict < on d2
// suffices. Block = 256 threads = 32 queries x 8 parts; grid (64, 8).
// Arithmetic is bit-identical to the reference path.
// ---------------------------------------------------------------------------
__global__ void __launch_bounds__(256) knn_part_kernel(const float* __restrict__ coords) {
    __shared__ float4 sp[NP];              // {x, y, z, sq}, 32 KB
    const int b   = blockIdx.y;
    const int tid = threadIdx.x;
    const float* cb = coords + b * 3 * NP;
    for (int i = tid; i < NP; i += 256) {
        float x = cb[i], y = cb[NP + i], z = cb[2 * NP + i];
        float sq = __fadd_rn(__fadd_rn(__fmul_rn(x, x), __fmul_rn(y, y)),
                             __fmul_rn(z, z));
        sp[i] = make_float4(x, y, z, sq);
    }
    __syncthreads();

    const int part = tid & (NPART - 1);
    const int n    = blockIdx.x * 32 + (tid >> 3);
    const float4 q = sp[n];
    const float qs = q.w;

    float bd[KK];
    int   bi[KK];
#pragma unroll
    for (int k = 0; k < KK; k++) { bd[k] = FINF; bi[k] = 0; }
    float thr = FINF;

    const int j0 = part * CHUNK;
#pragma unroll 4
    for (int jj = 0; jj < CHUNK; jj++) {
        const int j = j0 + jj;
        float4 p = sp[j];
        float dot = __fmaf_rn(q.z, p.z, __fmaf_rn(q.y, p.y, __fmul_rn(q.x, p.x)));
        float d = __fsub_rn(__fadd_rn(qs, p.w), __fmul_rn(2.0f, dot));
        if (d < thr) {                      // strict: equal keeps earlier index
            int pos = KK - 1;
            while (pos > 0 && bd[pos - 1] > d) {
                bd[pos] = bd[pos - 1]; bi[pos] = bi[pos - 1]; pos--;
            }
            bd[pos] = d; bi[pos] = j;
            thr = bd[KK - 1];
        }
    }

    const int base = ((b * NP + n) * NPART + part) * KK;
#pragma unroll
    for (int k = 0; k < KK; k++) {
        g_pd[base + k] = bd[k];
        g_pi[base + k] = bi[k];
    }
}

// ---------------------------------------------------------------------------
// Kernel 1b: exact 8-way merge on (d2, idx) lexicographic -> global stable
// top-16 (== jax.lax.top_k order). Writes g_idx and local_coords.
// One thread per query; block 128 (one batch per block, coords in SMEM).
// ---------------------------------------------------------------------------
__global__ void __launch_bounds__(128) knn_merge_kernel(const float* __restrict__ coords,
                                                        float* __restrict__ out) {
    const int qg = blockIdx.x * 128 + threadIdx.x;   // 0 .. B*N-1
    const int b  = qg >> 11;
    const int n  = qg & (NP - 1);

    __shared__ float sc[3 * NP];                     // 24 KB, batch coords
    const float* cb = coords + b * 3 * NP;
    for (int i = threadIdx.x; i < 3 * NP; i += 128) sc[i] = cb[i];
    __syncthreads();

    const int base = (b * NP + n) * NPART * KK;
    int   h[NPART];
    float hd[NPART];
    int   hi[NPART];
#pragma unroll
    for (int p = 0; p < NPART; p++) {
        h[p]  = 0;
        hd[p] = g_pd[base + p * KK];
        hi[p] = g_pi[base + p * KK];
    }

    const float qx = sc[n], qy = sc[NP + n], qz = sc[2 * NP + n];
    float lx[KK], ly[KK], lz[KK];
    int* gi = g_idx + (b * NP + n) * KK;

#pragma unroll
    for (int k = 0; k < KK; k++) {
        int   bp = 0;
        float bdv = hd[0];
        int   biv = hi[0];
#pragma unroll
        for (int p = 1; p < NPART; p++) {
            bool better = (hd[p] < bdv) || (hd[p] == bdv && hi[p] < biv);
            if (better) { bp = p; bdv = hd[p]; biv = hi[p]; }
        }
        gi[k] = biv;
        lx[k] = qx - sc[biv];
        ly[k] = qy - sc[NP + biv];
        lz[k] = qz - sc[2 * NP + biv];
        int nh = ++h[bp];
        if (nh < KK) {
            hd[bp] = g_pd[base + bp * KK + nh];
            hi[bp] = g_pi[base + bp * KK + nh];
        } else {
            hd[bp] = FINF;
            hi[bp] = 0x7fffffff;
        }
    }

    float* lc = out + LC_OFF;
    float4* px = (float4*)(lc + ((b * 3 + 0) * NP + n) * KK);
    float4* py = (float4*)(lc + ((b * 3 + 1) * NP + n) * KK);
    float4* pz = (float4*)(lc + ((b * 3 + 2) * NP + n) * KK);
#pragma unroll
    for (int m = 0; m < 4; m++) {
        px[m] = make_float4(lx[4*m], lx[4*m+1], lx[4*m+2], lx[4*m+3]);
        py[m] = make_float4(ly[4*m], ly[4*m+1], ly[4*m+2], ly[4*m+3]);
        pz[m] = make_float4(lz[4*m], lz[4*m+1], lz[4*m+2], lz[4*m+3]);
    }
}

// ---------------------------------------------------------------------------
// Kernel 2: pointwise MLP  F[point][co] = relu(bn2(w2 @ relu(bn1(w1 @ x))))
// grid 128 blocks (128 points each), block 256 = 16(tx:co) x 16(ty:p),
// 8x8 register tile per thread, stride-16 blocking (conflict-free LDS).
// ---------------------------------------------------------------------------
#define W1S   0
#define W2S   8192
#define XSO   24576
#define HSO   32768
#define HSTR  129
#define S1S   49280
#define T1S   49408
#define S2S   49536
#define T2S   49664
#define SM2_FLOATS 49792

__global__ void __launch_bounds__(256) mlp_kernel(
    const float* __restrict__ x,
    const float* __restrict__ w1, const float* __restrict__ g1,
    const float* __restrict__ b1, const float* __restrict__ m1,
    const float* __restrict__ v1,
    const float* __restrict__ w2, const float* __restrict__ g2,
    const float* __restrict__ b2, const float* __restrict__ m2,
    const float* __restrict__ v2)
{
    extern __shared__ float sm[];
    const int t = threadIdx.x;

    if (t < CO) {
        float i1 = g1[t] / sqrtf(v1[t] + 1e-5f);
        sm[S1S + t] = i1;
        sm[T1S + t] = fmaf(-m1[t], i1, b1[t]);
        float i2 = g2[t] / sqrtf(v2[t] + 1e-5f);
        sm[S2S + t] = i2;
        sm[T2S + t] = fmaf(-m2[t], i2, b2[t]);
    }
    for (int i = t; i < CI * CO; i += 256)
        sm[W1S + i] = w1[(i & 127) * CI + (i >> 7)];
    for (int i = t; i < CO * CO; i += 256)
        sm[W2S + i] = w2[(i & 127) * CO + (i >> 7)];

    const int b  = blockIdx.x >> 4;
    const int n0 = (blockIdx.x & 15) << 7;
    for (int i = t; i < CI * 128; i += 256) {
        int c = i >> 7, p = i & 127;
        sm[XSO + i] = x[(b * CI + c) * NP + n0 + p];
    }
    __syncthreads();

    const int tx = t & 15, ty = t >> 4;
    float acc[8][8];
#pragma unroll
    for (int u = 0; u < 8; u++)
#pragma unroll
        for (int v = 0; v < 8; v++) acc[u][v] = 0.f;

    for (int c = 0; c < CI; c++) {
        float wv[8], xv[8];
#pragma unroll
        for (int u = 0; u < 8; u++) wv[u] = sm[W1S + c * 128 + tx + 16 * u];
#pragma unroll
        for (int v = 0; v < 8; v++) xv[v] = sm[XSO + c * 128 + ty + 16 * v];
#pragma unroll
        for (int u = 0; u < 8; u++)
#pragma unroll
            for (int v = 0; v < 8; v++)
                acc[u][v] = fmaf(wv[u], xv[v], acc[u][v]);
    }
#pragma unroll
    for (int u = 0; u < 8; u++) {
        int co = tx + 16 * u;
        float s = sm[S1S + co], o = sm[T1S + co];
#pragma unroll
        for (int v = 0; v < 8; v++) {
            float hvv = fmaxf(fmaf(acc[u][v], s, o), 0.f);
            sm[HSO + co * HSTR + ty + 16 * v] = hvv;
        }
    }
    __syncthreads();

#pragma unroll
    for (int u = 0; u < 8; u++)
#pragma unroll
        for (int v = 0; v < 8; v++) acc[u][v] = 0.f;

    for (int c = 0; c < CO; c++) {
        float wv[8], hv[8];
#pragma unroll
        for (int u = 0; u < 8; u++) wv[u] = sm[W2S + c * 128 + tx + 16 * u];
#pragma unroll
        for (int v = 0; v < 8; v++) hv[v] = sm[HSO + c * HSTR + ty + 16 * v];
#pragma unroll
        for (int u = 0; u < 8; u++)
#pragma unroll
            for (int v = 0; v < 8; v++)
                acc[u][v] = fmaf(wv[u], hv[v], acc[u][v]);
    }
    const int gpb = blockIdx.x * 128;
#pragma unroll
    for (int u = 0; u < 8; u++) {
        int co = tx + 16 * u;
        float s = sm[S2S + co], o = sm[T2S + co];
#pragma unroll
        for (int v = 0; v < 8; v++) {
            int p = ty + 16 * v;
            g_F[(gpb + p) * CO + co] = fmaxf(fmaf(acc[u][v], s, o), 0.f);
        }
    }
}

// ---------------------------------------------------------------------------
// Kernel 3: gather F rows by idx -> knn_mlp_x, running max -> y.
// One block (128 threads = co) per (b,n).
// ---------------------------------------------------------------------------
__global__ void __launch_bounds__(128) gather_kernel(float* __restrict__ out) {
    const int bn = blockIdx.x;             // 0 .. B*N-1
    const int b  = bn >> 11;
    const int n  = bn & (NP - 1);
    const int co = threadIdx.x;

    __shared__ int sidx[KK];
    if (co < KK) sidx[co] = g_idx[bn * KK + co];
    __syncthreads();

    const float* Fb = g_F + (b * NP) * CO + co;
    float v[KK];
    float mx = -FINF;
#pragma unroll
    for (int k = 0; k < KK; k++) {
        float val = Fb[sidx[k] * CO];
        v[k] = val;
        mx = fmaxf(mx, val);
    }
    float4* kp = (float4*)(out + KNN_OFF + ((b * CO + co) * NP + n) * KK);
    kp[0] = make_float4(v[0],  v[1],  v[2],  v[3]);
    kp[1] = make_float4(v[4],  v[5],  v[6],  v[7]);
    kp[2] = make_float4(v[8],  v[9],  v[10], v[11]);
    kp[3] = make_float4(v[12], v[13], v[14], v[15]);
    out[(b * CO + co) * NP + n] = mx;
}

// ---------------------------------------------------------------------------
extern "C" void kernel_launch(void* const* d_in, const int* in_sizes, int n_in,
                              void* d_out, int out_size) {
    const float* x      = (const float*)d_in[0];
    const float* coords = (const float*)d_in[1];
    const float* w1     = (const float*)d_in[2];
    const float* g1     = (const float*)d_in[3];
    const float* b1     = (const float*)d_in[4];
    const float* m1     = (const float*)d_in[5];
    const float* v1     = (const float*)d_in[6];
    const float* w2     = (const float*)d_in[7];
    const float* g2     = (const float*)d_in[8];
    const float* b2     = (const float*)d_in[9];
    const float* m2     = (const float*)d_in[10];
    const float* v2     = (const float*)d_in[11];
    float* out = (float*)d_out;

    cudaFuncSetAttribute(mlp_kernel, cudaFuncAttributeMaxDynamicSharedMemorySize,
                         SM2_FLOATS * 4);

    knn_part_kernel<<<dim3(64, BB), 256>>>(coords);
    mlp_kernel<<<128, 256, SM2_FLOATS * 4>>>(x, w1, g1, b1, m1, v1,
                                             w2, g2, b2, m2, v2);
    knn_merge_kernel<<<BB * NP / 128, 128>>>(coords, out);
    gather_kernel<<<BB * NP, 128>>>(out);
}